// round 4
// baseline (speedup 1.0000x reference)
#include <cuda_runtime.h>
#include <cstdint>
#include <cstddef>

// Problem constants (fixed shapes for this problem instance)
#define BB   8
#define LL   2048
#define KK   30          // TOP_K
#define FDIM 416         // 16 pos-emb + 25*16 RBF
#define CDIM 128         // EDGE_FEATURES

// ---------------------------------------------------------------------------
// Device scratch (no allocations allowed)
// ---------------------------------------------------------------------------
__device__ float g_atoms[(size_t)BB * LL * 15];   // per residue: Ca,N,C,O,Cb xyz
__device__ float g_ca[(size_t)BB * 3 * LL];       // SoA Ca coords per batch: [b][xyz][l]
__device__ int   g_eidx[(size_t)BB * LL * KK];    // top-k neighbor indices

// ---------------------------------------------------------------------------
// Kernel 1: virtual Cb + atom packing
// ---------------------------------------------------------------------------
__global__ void k_cb(const float* __restrict__ X) {
    int t = blockIdx.x * blockDim.x + threadIdx.x;
    if (t >= BB * LL) return;
    const float* x = X + (size_t)t * 12;
    float Nx = x[0],  Ny = x[1],  Nz = x[2];
    float Ax = x[3],  Ay = x[4],  Az = x[5];   // Ca
    float Cx = x[6],  Cy = x[7],  Cz = x[8];
    float Ox = x[9],  Oy = x[10], Oz = x[11];
    float bx = Ax - Nx, by = Ay - Ny, bz = Az - Nz;
    float cx = Cx - Ax, cy = Cy - Ay, cz = Cz - Az;
    float ax = by * cz - bz * cy;
    float ay = bz * cx - bx * cz;
    float az = bx * cy - by * cx;
    const float wa = -0.58273431f, wb = 0.56802827f, wc = -0.54067466f;
    float Bx = wa * ax + wb * bx + wc * cx + Ax;
    float By = wa * ay + wb * by + wc * cy + Ay;
    float Bz = wa * az + wb * bz + wc * cz + Az;
    float* a = g_atoms + (size_t)t * 15;
    // atom order matches the reference pair loop: [Ca, N, C, O, Cb]
    a[0]  = Ax; a[1]  = Ay; a[2]  = Az;
    a[3]  = Nx; a[4]  = Ny; a[5]  = Nz;
    a[6]  = Cx; a[7]  = Cy; a[8]  = Cz;
    a[9]  = Ox; a[10] = Oy; a[11] = Oz;
    a[12] = Bx; a[13] = By; a[14] = Bz;
    int bidx = t / LL, i = t - bidx * LL;
    g_ca[((size_t)bidx * 3 + 0) * LL + i] = Ax;
    g_ca[((size_t)bidx * 3 + 1) * LL + i] = Ay;
    g_ca[((size_t)bidx * 3 + 2) * LL + i] = Az;
}

// ---------------------------------------------------------------------------
// Kernel 2: masked pairwise Ca distances + exact top-K (ascending, stable ties)
// One block per (b, i) row. Packed u64 key = (float_bits(dist) << 32) | j
// gives min-dist with ties broken by smaller j == jax.lax.top_k semantics.
// ---------------------------------------------------------------------------
__global__ void __launch_bounds__(256) k_topk(const float* __restrict__ mask) {
    __shared__ float sx[LL], sy[LL], sz[LL], smk[LL], sd[LL];
    __shared__ float wred[8];
    __shared__ unsigned long long wkey[8];
    __shared__ float sDmax;

    int row = blockIdx.x;
    int bb  = row >> 11;          // row / LL
    int i   = row & (LL - 1);
    int tid = threadIdx.x;
    int lane = tid & 31, warp = tid >> 5;

    const float* cax = g_ca + (size_t)bb * 3 * LL;
    for (int j = tid; j < LL; j += 256) {
        sx[j]  = cax[j];
        sy[j]  = cax[LL + j];
        sz[j]  = cax[2 * LL + j];
        smk[j] = mask[(size_t)bb * LL + j];
    }
    __syncthreads();

    float cx = sx[i], cy = sy[i], cz = sz[i], mi = smk[i];

    // Pass 1: D = mask2d * sqrt(|dX|^2 + 1e-6), track row max
    float lmax = 0.f;
    for (int j = tid; j < LL; j += 256) {
        float dx = cx - sx[j], dy = cy - sy[j], dz = cz - sz[j];
        float d = mi * smk[j] * sqrtf(dx * dx + dy * dy + dz * dz + 1e-6f);
        sd[j] = d;
        lmax = fmaxf(lmax, d);
    }
#pragma unroll
    for (int off = 16; off; off >>= 1)
        lmax = fmaxf(lmax, __shfl_xor_sync(0xffffffffu, lmax, off));
    if (lane == 0) wred[warp] = lmax;
    __syncthreads();
    if (tid == 0) {
        float m = wred[0];
#pragma unroll
        for (int w = 1; w < 8; ++w) m = fmaxf(m, wred[w]);
        sDmax = m;
    }
    __syncthreads();
    float Dmax = sDmax;

    // Pass 2: D_adjust = D + (1 - mask2d) * Dmax  (in-place, own slots only)
    for (int j = tid; j < LL; j += 256) {
        float m2 = mi * smk[j];
        sd[j] = sd[j] + (1.f - m2) * Dmax;
    }
    __syncthreads();

    // KK iterative argmin extractions
    for (int s = 0; s < KK; ++s) {
        unsigned long long best = ~0ull;
        for (int j = tid; j < LL; j += 256) {
            unsigned long long key =
                ((unsigned long long)__float_as_uint(sd[j]) << 32) | (unsigned)j;
            if (key < best) best = key;
        }
#pragma unroll
        for (int off = 16; off; off >>= 1) {
            unsigned long long o2 = __shfl_xor_sync(0xffffffffu, best, off);
            if (o2 < best) best = o2;
        }
        if (lane == 0) wkey[warp] = best;
        __syncthreads();
        if (tid == 0) {
            unsigned long long m = wkey[0];
#pragma unroll
            for (int w = 1; w < 8; ++w)
                if (wkey[w] < m) m = wkey[w];
            int jsel = (int)(m & 0xffffffffu);
            g_eidx[(size_t)row * KK + s] = jsel;
            sd[jsel] = __int_as_float(0x7f800000);  // +inf -> removed
        }
        __syncthreads();
    }
}

// ---------------------------------------------------------------------------
// Kernel 3: edge features (pos-emb + 25x16 RBF) -> [30 x 416] @ W_e [416 x 128]
//           -> LayerNorm -> output. One block per (b, i) row, 128 threads
//           (thread == output channel). GEMM via packed fma.rn.f32x2 (FFMA2).
// ---------------------------------------------------------------------------
struct S3 {
    float feat[FDIM][32];   // [feature][edge], edges 30..31 zero-padded; 128B rows
    float ajs[KK][16];      // gathered neighbor atoms (15 floats used)
    float ais[16];          // residue-i atoms
    float red[KK][8];       // LN partials: [k][warp] sum, [k][4+warp] sumsq
    float mu_s[KK];
    float rs_s[KK];
    int   idxs[KK];
    int   dpe[KK];
};

__global__ void __launch_bounds__(128) k_edge(
    const int*   __restrict__ ridx,
    const int*   __restrict__ chains,
    const float* __restrict__ We,
    const float* __restrict__ be,
    const float* __restrict__ ge,
    const float* __restrict__ beln,
    const float* __restrict__ Wpe,
    const float* __restrict__ bpe,
    float* __restrict__ outE,
    float* __restrict__ outI)
{
    extern __shared__ unsigned char smem_raw[];
    S3* s = reinterpret_cast<S3*>(smem_raw);

    int row = blockIdx.x;
    int bb  = row >> 11;
    int i   = row & (LL - 1);
    int tid = threadIdx.x;
    int lane = tid & 31, warp = tid >> 5;

    if (tid < 15) s->ais[tid] = g_atoms[(size_t)row * 15 + tid];
    if (tid < KK) {
        int j = g_eidx[(size_t)row * KK + tid];
        s->idxs[tid] = j;
        int ri = ridx[(size_t)bb * LL + i];
        int rj = ridx[(size_t)bb * LL + j];
        int ec = (chains[(size_t)bb * LL + i] == chains[(size_t)bb * LL + j]);
        int off = ri - rj + 32;
        off = off < 0 ? 0 : (off > 64 ? 64 : off);
        s->dpe[tid] = ec ? off : 65;
    }
    __syncthreads();

    // Gather neighbor atoms (30 x 15 floats)
    for (int t = tid; t < KK * 15; t += CDIM) {
        int k = t / 15, c = t - k * 15;
        s->ajs[k][c] = g_atoms[((size_t)bb * LL + s->idxs[k]) * 15 + c];
    }
    // Positional-embedding features: feat[p][k] = W_pe[d,p] + b_pe[p], p=0..15
    for (int t = tid; t < KK * 16; t += CDIM) {
        int k = t % KK, p = t / KK;
        s->feat[p][k] = Wpe[s->dpe[k] * 16 + p] + bpe[p];
    }
    // Zero-pad edge columns 30, 31 (for f32x2 pairing)
    for (int t = tid; t < FDIM * 2; t += CDIM)
        s->feat[t >> 1][30 + (t & 1)] = 0.f;
    __syncthreads();

    // RBF features: 30 edges x 25 atom pairs x 16 gaussians
    for (int t = tid; t < KK * 25; t += CDIM) {
        int k  = t % KK, pr = t / KK;
        int ai = pr / 5, aj = pr % 5;
        float dx = s->ais[ai * 3 + 0] - s->ajs[k][aj * 3 + 0];
        float dy = s->ais[ai * 3 + 1] - s->ajs[k][aj * 3 + 1];
        float dz = s->ais[ai * 3 + 2] - s->ajs[k][aj * 3 + 2];
        float d = sqrtf(dx * dx + dy * dy + dz * dz + 1e-6f);
        int fb = 16 + pr * 16;
#pragma unroll
        for (int m = 0; m < 16; ++m) {
            float mu = 2.0f + 1.33333333f * (float)m;   // linspace(2,22,16)
            float u  = (d - mu) * 0.8f;                 // / sigma (1.25)
            s->feat[fb + m][k] = __expf(-u * u);
        }
    }
    __syncthreads();

    // GEMM: thread `o` computes E[k][o] for all 30 edges via packed f32x2 FMA.
    int o = tid;
    unsigned long long acc[16];
#pragma unroll
    for (int q = 0; q < 16; ++q) acc[q] = 0ull;

    const float* Wc = We + o;
#pragma unroll 4
    for (int f = 0; f < FDIM; ++f) {
        float w = Wc[(size_t)f * CDIM];
        unsigned long long w2;
        asm("mov.b64 %0, {%1, %1};" : "=l"(w2) : "r"(__float_as_uint(w)));
        const ulonglong2* fr = reinterpret_cast<const ulonglong2*>(&s->feat[f][0]);
#pragma unroll
        for (int q = 0; q < 8; ++q) {
            ulonglong2 v = fr[q];   // LDS.128 broadcast: edges 4q..4q+3
            asm("fma.rn.f32x2 %0, %1, %2, %0;" : "+l"(acc[2 * q])     : "l"(v.x), "l"(w2));
            asm("fma.rn.f32x2 %0, %1, %2, %0;" : "+l"(acc[2 * q + 1]) : "l"(v.y), "l"(w2));
        }
    }

    // Unpack accumulators + bias
    float ev[KK];
    float beo = be[o];
#pragma unroll
    for (int q = 0; q < 15; ++q) {
        unsigned lo, hi;
        asm("mov.b64 {%0, %1}, %2;" : "=r"(lo), "=r"(hi) : "l"(acc[q]));
        ev[2 * q]     = __uint_as_float(lo) + beo;
        ev[2 * q + 1] = __uint_as_float(hi) + beo;
    }

    // LayerNorm over channels (across the 128 threads)
#pragma unroll
    for (int k = 0; k < KK; ++k) {
        float v = ev[k];
        float s1 = v, s2 = v * v;
#pragma unroll
        for (int off = 16; off; off >>= 1) {
            s1 += __shfl_xor_sync(0xffffffffu, s1, off);
            s2 += __shfl_xor_sync(0xffffffffu, s2, off);
        }
        if (lane == 0) { s->red[k][warp] = s1; s->red[k][4 + warp] = s2; }
    }
    __syncthreads();
    if (tid < KK) {
        float s1 = s->red[tid][0] + s->red[tid][1] + s->red[tid][2] + s->red[tid][3];
        float s2 = s->red[tid][4] + s->red[tid][5] + s->red[tid][6] + s->red[tid][7];
        float mu  = s1 * (1.f / 128.f);
        float var = s2 * (1.f / 128.f) - mu * mu;
        s->mu_s[tid] = mu;
        s->rs_s[tid] = rsqrtf(var + 1e-5f);
    }
    __syncthreads();

    float go = ge[o], blo = beln[o];
    size_t base = (size_t)row * KK * CDIM;
#pragma unroll
    for (int k = 0; k < KK; ++k)
        outE[base + k * CDIM + o] = (ev[k] - s->mu_s[k]) * s->rs_s[k] * go + blo;

    if (outI != nullptr && tid < KK)
        outI[(size_t)row * KK + tid] = (float)s->idxs[tid];
}

// ---------------------------------------------------------------------------
// Launch
// ---------------------------------------------------------------------------
extern "C" void kernel_launch(void* const* d_in, const int* in_sizes, int n_in,
                              void* d_out, int out_size) {
    const float* X      = (const float*)d_in[0];
    const float* mask   = (const float*)d_in[1];
    const int*   ridx   = (const int*)  d_in[2];
    const int*   chains = (const int*)  d_in[3];
    const float* We     = (const float*)d_in[4];
    const float* be     = (const float*)d_in[5];
    const float* ge     = (const float*)d_in[6];
    const float* beln   = (const float*)d_in[7];
    const float* Wpe    = (const float*)d_in[8];
    const float* bpe    = (const float*)d_in[9];
    float* out = (float*)d_out;

    const size_t E_ELEMS = (size_t)BB * LL * KK * CDIM;   // 62,914,560
    const size_t I_ELEMS = (size_t)BB * LL * KK;          //    491,520
    float* outI = ((size_t)out_size >= E_ELEMS + I_ELEMS) ? (out + E_ELEMS)
                                                          : nullptr;

    cudaFuncSetAttribute(k_edge, cudaFuncAttributeMaxDynamicSharedMemorySize,
                         (int)sizeof(S3));

    k_cb<<<(BB * LL + 255) / 256, 256>>>(X);
    k_topk<<<BB * LL, 256>>>(mask);
    k_edge<<<BB * LL, 128, sizeof(S3)>>>(ridx, chains, We, be, ge, beln,
                                         Wpe, bpe, out, outI);
}

// round 8
// speedup vs baseline: 1.3906x; 1.3906x over previous
#include <cuda_runtime.h>
#include <cuda_bf16.h>
#include <cstdint>
#include <cstddef>

#define BB   8
#define LL   2048
#define KK   30
#define FDIM 416
#define CDIM 128
#define RPB  2            // residue rows per CTA in k_edge3 (M = 64)
#define NCHK 13           // K chunks of 32 features (13*32 = 416)

// ---------------------------------------------------------------------------
// Device scratch
// ---------------------------------------------------------------------------
__device__ float g_atoms[(size_t)BB * LL * 15];
__device__ float g_ca[(size_t)BB * 3 * LL];
__device__ int   g_eidx[(size_t)BB * LL * KK];
// Pre-split W_e, k-paired: g_Wb{h,l}[c][kp][n] = bf16x2(W[32c+2kp][n], W[32c+2kp+1][n])
__device__ uint32_t g_Wbh[NCHK][16][128];
__device__ uint32_t g_Wbl[NCHK][16][128];

// ---------------------------------------------------------------------------
// mma.sync wrapper (baseline PTX, works on compute_103)
// ---------------------------------------------------------------------------
__device__ __forceinline__ void mma16816(float* c, uint32_t a0, uint32_t a1,
                                         uint32_t a2, uint32_t a3,
                                         uint32_t b0, uint32_t b1) {
    asm volatile(
        "mma.sync.aligned.m16n8k16.row.col.f32.bf16.bf16.f32 "
        "{%0,%1,%2,%3}, {%4,%5,%6,%7}, {%8,%9}, {%0,%1,%2,%3};"
        : "+f"(c[0]), "+f"(c[1]), "+f"(c[2]), "+f"(c[3])
        : "r"(a0), "r"(a1), "r"(a2), "r"(a3), "r"(b0), "r"(b1));
}

// ---------------------------------------------------------------------------
// k_packW: split W_e to bf16 hi/lo, k-paired layout (runs every launch)
// ---------------------------------------------------------------------------
__global__ void k_packW(const float* __restrict__ We) {
    int t = blockIdx.x * 256 + threadIdx.x;
    if (t >= NCHK * 16 * 128) return;
    int c  = t >> 11;
    int kp = (t >> 7) & 15;
    int n  = t & 127;
    int k0 = c * 32 + 2 * kp;
    float w0 = We[(size_t)k0 * CDIM + n];
    float w1 = We[(size_t)(k0 + 1) * CDIM + n];
    __nv_bfloat16 h0 = __float2bfloat16(w0);
    __nv_bfloat16 h1 = __float2bfloat16(w1);
    __nv_bfloat16 l0 = __float2bfloat16(w0 - __bfloat162float(h0));
    __nv_bfloat16 l1 = __float2bfloat16(w1 - __bfloat162float(h1));
    g_Wbh[c][kp][n] = (uint32_t)__bfloat16_as_ushort(h0) |
                      ((uint32_t)__bfloat16_as_ushort(h1) << 16);
    g_Wbl[c][kp][n] = (uint32_t)__bfloat16_as_ushort(l0) |
                      ((uint32_t)__bfloat16_as_ushort(l1) << 16);
}

// ---------------------------------------------------------------------------
// k_cb: virtual Cb + atom packing
// ---------------------------------------------------------------------------
__global__ void k_cb(const float* __restrict__ X) {
    int t = blockIdx.x * blockDim.x + threadIdx.x;
    if (t >= BB * LL) return;
    const float* x = X + (size_t)t * 12;
    float Nx = x[0],  Ny = x[1],  Nz = x[2];
    float Ax = x[3],  Ay = x[4],  Az = x[5];
    float Cx = x[6],  Cy = x[7],  Cz = x[8];
    float Ox = x[9],  Oy = x[10], Oz = x[11];
    float bx = Ax - Nx, by = Ay - Ny, bz = Az - Nz;
    float cx = Cx - Ax, cy = Cy - Ay, cz = Cz - Az;
    float ax = by * cz - bz * cy;
    float ay = bz * cx - bx * cz;
    float az = bx * cy - by * cx;
    const float wa = -0.58273431f, wb = 0.56802827f, wc = -0.54067466f;
    float Bx = wa * ax + wb * bx + wc * cx + Ax;
    float By = wa * ay + wb * by + wc * cy + Ay;
    float Bz = wa * az + wb * bz + wc * cz + Az;
    float* a = g_atoms + (size_t)t * 15;
    a[0]  = Ax; a[1]  = Ay; a[2]  = Az;
    a[3]  = Nx; a[4]  = Ny; a[5]  = Nz;
    a[6]  = Cx; a[7]  = Cy; a[8]  = Cz;
    a[9]  = Ox; a[10] = Oy; a[11] = Oz;
    a[12] = Bx; a[13] = By; a[14] = Bz;
    int bidx = t / LL, i = t - bidx * LL;
    g_ca[((size_t)bidx * 3 + 0) * LL + i] = Ax;
    g_ca[((size_t)bidx * 3 + 1) * LL + i] = Ay;
    g_ca[((size_t)bidx * 3 + 2) * LL + i] = Az;
}

// ---------------------------------------------------------------------------
// k_topk: exact top-K, register-resident keys; also emits E_idx floats
// ---------------------------------------------------------------------------
__global__ void __launch_bounds__(256) k_topk(const float* __restrict__ mask,
                                              float* __restrict__ outI) {
    __shared__ float sx[LL], sy[LL], sz[LL], smk[LL];
    __shared__ float wred[8], sDmax;
    __shared__ unsigned long long wkey[8], swin;

    int row = blockIdx.x;
    int bb  = row >> 11;
    int i   = row & (LL - 1);
    int tid = threadIdx.x;
    int lane = tid & 31, warp = tid >> 5;

    const float* cax = g_ca + (size_t)bb * 3 * LL;
    for (int j = tid; j < LL; j += 256) {
        sx[j]  = cax[j];
        sy[j]  = cax[LL + j];
        sz[j]  = cax[2 * LL + j];
        smk[j] = mask[(size_t)bb * LL + j];
    }
    __syncthreads();

    float cx = sx[i], cy = sy[i], cz = sz[i], mi = smk[i];

    float d[8];
    float lmax = 0.f;
#pragma unroll
    for (int q = 0; q < 8; ++q) {
        int j = tid + 256 * q;
        float dx = cx - sx[j], dy = cy - sy[j], dz = cz - sz[j];
        d[q] = mi * smk[j] * sqrtf(dx * dx + dy * dy + dz * dz + 1e-6f);
        lmax = fmaxf(lmax, d[q]);
    }
#pragma unroll
    for (int off = 16; off; off >>= 1)
        lmax = fmaxf(lmax, __shfl_xor_sync(0xffffffffu, lmax, off));
    if (lane == 0) wred[warp] = lmax;
    __syncthreads();
    if (tid == 0) {
        float m = wred[0];
#pragma unroll
        for (int w = 1; w < 8; ++w) m = fmaxf(m, wred[w]);
        sDmax = m;
    }
    __syncthreads();
    float Dmax = sDmax;

    unsigned long long key[8];
#pragma unroll
    for (int q = 0; q < 8; ++q) {
        int j = tid + 256 * q;
        float da = d[q] + (1.f - mi * smk[j]) * Dmax;
        key[q] = ((unsigned long long)__float_as_uint(da) << 32) | (unsigned)j;
    }

    for (int s = 0; s < KK; ++s) {
        unsigned long long best = key[0];
#pragma unroll
        for (int q = 1; q < 8; ++q) if (key[q] < best) best = key[q];
#pragma unroll
        for (int off = 16; off; off >>= 1) {
            unsigned long long o2 = __shfl_xor_sync(0xffffffffu, best, off);
            if (o2 < best) best = o2;
        }
        if (lane == 0) wkey[warp] = best;
        __syncthreads();
        if (tid == 0) {
            unsigned long long m = wkey[0];
#pragma unroll
            for (int w = 1; w < 8; ++w) if (wkey[w] < m) m = wkey[w];
            swin = m;
            int jsel = (int)(m & 0xffffffffu);
            g_eidx[(size_t)row * KK + s] = jsel;
            if (outI) outI[(size_t)row * KK + s] = (float)jsel;
        }
        __syncthreads();
        unsigned long long wv = swin;
        if (((int)(wv & 255u)) == tid) {         // j = tid + 256*q
            int slot = (int)((wv >> 8) & 7u);
#pragma unroll
            for (int q = 0; q < 8; ++q)
                if (q == slot) key[q] = ~0ull;
        }
    }
}

// ---------------------------------------------------------------------------
// k_edge3: bf16-split mma.sync edge GEMM.
// CTA = 2 rows -> M=64 edge slots (2x32, edges 30/31 zero), N=128, K=416.
// Warp w owns channels [32w, 32w+32). A rebuilt per 32-feature chunk.
// ---------------------------------------------------------------------------
__global__ void __launch_bounds__(128)
k_edge3(const int*   __restrict__ ridx,
        const int*   __restrict__ chains,
        const float* __restrict__ be,
        const float* __restrict__ ge,
        const float* __restrict__ bln,
        const float* __restrict__ Wpe,
        const float* __restrict__ bpe,
        float* __restrict__ outE)
{
    __shared__ float    s_ds[25 * 64];      // pair distances [pr][m]
    __shared__ float    s_pe[64 * 16];      // pos-emb [m][p]
    __shared__ float    s_ajs[60 * 16];     // neighbor atoms [r*30+k][15]
    __shared__ float    s_ais[2 * 16];      // own atoms
    __shared__ int      s_idx[64];
    __shared__ int      s_dpe[64];
    __shared__ float    s_be[128], s_ge[128], s_bln[128];
    __shared__ uint32_t s_ah[16 * 65];      // A hi: [kp][m], stride 65
    __shared__ uint32_t s_al[16 * 65];
    __shared__ uint32_t s_bh[16 * 129];     // B hi: [kp][n], stride 129
    __shared__ uint32_t s_bl[16 * 129];
    __shared__ float    s_rsum[64 * 4], s_rsq[64 * 4];
    __shared__ float    s_mu[64], s_rs[64];

    int tid  = threadIdx.x;
    int lane = tid & 31, w = tid >> 5;
    int g    = lane >> 2, tig = lane & 3;
    int row0 = blockIdx.x * RPB;
    int bb   = row0 >> 11;

    // ---- prologue ----
    s_be[tid]  = be[tid];
    s_ge[tid]  = ge[tid];
    s_bln[tid] = bln[tid];
    if (tid < 64) {
        int r = tid >> 5, k = tid & 31;
        int grow = row0 + r;
        int li = grow & (LL - 1);
        int j = (k < KK) ? g_eidx[(size_t)grow * KK + k] : 0;
        s_idx[tid] = j;
        int ri = ridx[(size_t)bb * LL + li];
        int rj = ridx[(size_t)bb * LL + j];
        int ec = (chains[(size_t)bb * LL + li] == chains[(size_t)bb * LL + j]);
        int off = ri - rj + 32;
        off = off < 0 ? 0 : (off > 64 ? 64 : off);
        s_dpe[tid] = ec ? off : 65;
    }
    if (tid < 30) {
        int r = tid / 15, c = tid - r * 15;
        s_ais[r * 16 + c] = g_atoms[(size_t)(row0 + r) * 15 + c];
    }
    __syncthreads();

    for (int t = tid; t < 2 * KK * 15; t += 128) {   // 900 neighbor-atom loads
        int k2 = t / 15, c = t - k2 * 15;
        int r = k2 / KK, kk = k2 - r * KK;
        s_ajs[(r * KK + kk) * 16 + c] =
            g_atoms[((size_t)bb * LL + s_idx[r * 32 + kk]) * 15 + c];
    }
    __syncthreads();

    for (int t = tid; t < 25 * 64; t += 128) {       // pair distances
        int m = t & 63, pr = t >> 6;
        int r = m >> 5, k = m & 31;
        float dv = 0.f;
        if (k < KK) {
            int ai = pr / 5, aj = pr - (pr / 5) * 5;
            const float* A = s_ais + r * 16 + ai * 3;
            const float* J = s_ajs + (r * KK + k) * 16 + aj * 3;
            float dx = A[0] - J[0], dy = A[1] - J[1], dz = A[2] - J[2];
            dv = sqrtf(dx * dx + dy * dy + dz * dz + 1e-6f);
        }
        s_ds[pr * 64 + m] = dv;
    }
    for (int t = tid; t < 64 * 16; t += 128) {       // pos-emb
        int m = t & 63, p = t >> 6;
        int k = m & 31;
        float v = 0.f;
        if (k < KK) v = Wpe[s_dpe[m] * 16 + p] + bpe[p];
        s_pe[m * 16 + p] = v;
    }
    __syncthreads();

    // ---- accumulators: c[mt][nt][4] ----
    float acc[4][4][4];
#pragma unroll
    for (int mt = 0; mt < 4; ++mt)
#pragma unroll
        for (int nt = 0; nt < 4; ++nt)
#pragma unroll
            for (int q = 0; q < 4; ++q) acc[mt][nt][q] = 0.f;

    const int am   = tid & 63;          // A-build: this thread's edge slot
    const int ahalf = tid >> 6;         // kp 0..7 or 8..15
    const int apad = ((am & 31) >= KK);

    for (int c = 0; c < NCHK; ++c) {
        // B chunk copy (pre-split, pre-paired)
        {
            const uint32_t* gh = &g_Wbh[c][0][0];
            const uint32_t* gl = &g_Wbl[c][0][0];
#pragma unroll
            for (int q = 0; q < 16; ++q) {
                int e = tid + 128 * q;
                int kp = e >> 7, n = e & 127;
                s_bh[kp * 129 + n] = gh[e];
                s_bl[kp * 129 + n] = gl[e];
            }
        }
        // A chunk build: 8 kp x 2 features per thread
#pragma unroll
        for (int kp8 = 0; kp8 < 8; ++kp8) {
            int kp = ahalf * 8 + kp8;
            uint32_t hp = 0, lp = 0;
#pragma unroll
            for (int e = 0; e < 2; ++e) {
                int gf = c * 32 + 2 * kp + e;
                float v;
                if (gf < 16) {
                    v = s_pe[am * 16 + gf];
                } else {
                    int t2 = gf - 16;
                    int pr = t2 >> 4, mm = t2 & 15;
                    float dd = s_ds[pr * 64 + am];
                    float u = (dd - (2.0f + 1.33333333f * (float)mm)) * 0.8f;
                    v = __expf(-u * u);
                }
                if (apad) v = 0.f;
                __nv_bfloat16 h = __float2bfloat16(v);
                __nv_bfloat16 l = __float2bfloat16(v - __bfloat162float(h));
                hp |= (uint32_t)__bfloat16_as_ushort(h) << (16 * e);
                lp |= (uint32_t)__bfloat16_as_ushort(l) << (16 * e);
            }
            s_ah[kp * 65 + am] = hp;
            s_al[kp * 65 + am] = lp;
        }
        __syncthreads();

        // 2 k16 steps per chunk
#pragma unroll
        for (int s = 0; s < 2; ++s) {
            int kpa = s * 8 + tig;      // A/B frag kp for k-low
            uint32_t ah[4][4], al[4][4];
#pragma unroll
            for (int mt = 0; mt < 4; ++mt) {
                int mb = mt * 16 + g;
                ah[mt][0] = s_ah[kpa * 65 + mb];
                ah[mt][1] = s_ah[kpa * 65 + mb + 8];
                ah[mt][2] = s_ah[(kpa + 4) * 65 + mb];
                ah[mt][3] = s_ah[(kpa + 4) * 65 + mb + 8];
                al[mt][0] = s_al[kpa * 65 + mb];
                al[mt][1] = s_al[kpa * 65 + mb + 8];
                al[mt][2] = s_al[(kpa + 4) * 65 + mb];
                al[mt][3] = s_al[(kpa + 4) * 65 + mb + 8];
            }
#pragma unroll
            for (int nt = 0; nt < 4; ++nt) {
                int nb = w * 32 + nt * 8 + g;
                uint32_t bh0 = s_bh[kpa * 129 + nb];
                uint32_t bh1 = s_bh[(kpa + 4) * 129 + nb];
                uint32_t bl0 = s_bl[kpa * 129 + nb];
                uint32_t bl1 = s_bl[(kpa + 4) * 129 + nb];
#pragma unroll
                for (int mt = 0; mt < 4; ++mt) {
                    mma16816(acc[mt][nt], ah[mt][0], ah[mt][1], ah[mt][2], ah[mt][3], bh0, bh1);
                    mma16816(acc[mt][nt], ah[mt][0], ah[mt][1], ah[mt][2], ah[mt][3], bl0, bl1);
                    mma16816(acc[mt][nt], al[mt][0], al[mt][1], al[mt][2], al[mt][3], bh0, bh1);
                }
            }
        }
        __syncthreads();
    }

    // ---- epilogue: + bias, LayerNorm over 128 channels per edge ----
    // lane's values: m in {mt*16+g, mt*16+g+8}, n in {nb+2tig, nb+2tig+1}
#pragma unroll
    for (int mt = 0; mt < 4; ++mt)
#pragma unroll
        for (int nt = 0; nt < 4; ++nt) {
            int n0 = w * 32 + nt * 8 + tig * 2;
            acc[mt][nt][0] += s_be[n0];
            acc[mt][nt][1] += s_be[n0 + 1];
            acc[mt][nt][2] += s_be[n0];
            acc[mt][nt][3] += s_be[n0 + 1];
        }

    // per-lane partial sums over its n for each of its 8 m rows
#pragma unroll
    for (int mt = 0; mt < 4; ++mt) {
        float s0 = 0.f, q0 = 0.f, s1 = 0.f, q1 = 0.f;   // rows g, g+8
#pragma unroll
        for (int nt = 0; nt < 4; ++nt) {
            float a0 = acc[mt][nt][0], a1 = acc[mt][nt][1];
            float a2 = acc[mt][nt][2], a3 = acc[mt][nt][3];
            s0 += a0 + a1;  q0 += a0 * a0 + a1 * a1;
            s1 += a2 + a3;  q1 += a2 * a2 + a3 * a3;
        }
        // reduce over tig (4 lanes, same g)
#pragma unroll
        for (int off = 1; off < 4; off <<= 1) {
            s0 += __shfl_xor_sync(0xffffffffu, s0, off);
            q0 += __shfl_xor_sync(0xffffffffu, q0, off);
            s1 += __shfl_xor_sync(0xffffffffu, s1, off);
            q1 += __shfl_xor_sync(0xffffffffu, q1, off);
        }
        if (tig == 0) {
            int m0 = mt * 16 + g;
            s_rsum[m0 * 4 + w] = s0;  s_rsq[m0 * 4 + w] = q0;
            s_rsum[(m0 + 8) * 4 + w] = s1;  s_rsq[(m0 + 8) * 4 + w] = q1;
        }
    }
    __syncthreads();
    if (tid < 64) {
        float s1 = s_rsum[tid * 4] + s_rsum[tid * 4 + 1] +
                   s_rsum[tid * 4 + 2] + s_rsum[tid * 4 + 3];
        float q1 = s_rsq[tid * 4] + s_rsq[tid * 4 + 1] +
                   s_rsq[tid * 4 + 2] + s_rsq[tid * 4 + 3];
        float mu = s1 * (1.f / 128.f);
        float var = q1 * (1.f / 128.f) - mu * mu;
        s_mu[tid] = mu;
        s_rs[tid] = rsqrtf(var + 1e-5f);
    }
    __syncthreads();

#pragma unroll
    for (int mt = 0; mt < 4; ++mt) {
#pragma unroll
        for (int half = 0; half < 2; ++half) {
            int m = mt * 16 + g + 8 * half;
            int k = m & 31;
            if (k >= KK) continue;
            int r = m >> 5;
            float mu = s_mu[m], rs = s_rs[m];
            size_t ebase = (((size_t)(row0 + r)) * KK + k) * CDIM;
#pragma unroll
            for (int nt = 0; nt < 4; ++nt) {
                int n0 = w * 32 + nt * 8 + tig * 2;
                float v0 = acc[mt][nt][2 * half];
                float v1 = acc[mt][nt][2 * half + 1];
                float2 o;
                o.x = (v0 - mu) * rs * s_ge[n0]     + s_bln[n0];
                o.y = (v1 - mu) * rs * s_ge[n0 + 1] + s_bln[n0 + 1];
                *(float2*)(outE + ebase + n0) = o;
            }
        }
    }
}

// ---------------------------------------------------------------------------
// Launch
// ---------------------------------------------------------------------------
extern "C" void kernel_launch(void* const* d_in, const int* in_sizes, int n_in,
                              void* d_out, int out_size) {
    const float* X      = (const float*)d_in[0];
    const float* mask   = (const float*)d_in[1];
    const int*   ridx   = (const int*)  d_in[2];
    const int*   chains = (const int*)  d_in[3];
    const float* We     = (const float*)d_in[4];
    const float* be     = (const float*)d_in[5];
    const float* ge     = (const float*)d_in[6];
    const float* beln   = (const float*)d_in[7];
    const float* Wpe    = (const float*)d_in[8];
    const float* bpe    = (const float*)d_in[9];
    float* out = (float*)d_out;

    const size_t E_ELEMS = (size_t)BB * LL * KK * CDIM;
    const size_t I_ELEMS = (size_t)BB * LL * KK;
    float* outI = ((size_t)out_size >= E_ELEMS + I_ELEMS) ? (out + E_ELEMS)
                                                          : nullptr;

    k_packW<<<(NCHK * 16 * 128 + 255) / 256, 256>>>(We);
    k_cb<<<(BB * LL + 255) / 256, 256>>>(X);
    k_topk<<<BB * LL, 256>>>(mask, outI);
    k_edge3<<<BB * LL / RPB, 128>>>(ridx, chains, be, ge, beln, Wpe, bpe, out);
}

// round 9
// speedup vs baseline: 1.7479x; 1.2569x over previous
#include <cuda_runtime.h>
#include <cuda_bf16.h>
#include <cstdint>
#include <cstddef>

#define BB   8
#define LL   2048
#define KK   30
#define FDIM 416
#define CDIM 128
#define RPB  2            // residue rows per CTA in k_edge3 (M = 64)
#define NCHK 13           // K chunks of 32 features (13*32 = 416)
#define AS   72           // A smem stride (u32): 72 mod 32 = 8 -> conflict-free
#define BS   136          // B smem stride (u32): 136 mod 32 = 8 -> conflict-free

// ---------------------------------------------------------------------------
// Device scratch
// ---------------------------------------------------------------------------
__device__ float g_atoms[(size_t)BB * LL * 15];
__device__ float g_ca[(size_t)BB * 3 * LL];
__device__ int   g_eidx[(size_t)BB * LL * KK];
// Pre-split W_e, k-paired: g_Wb{h,l}[c][kp][n] = bf16x2(W[32c+2kp][n], W[32c+2kp+1][n])
__device__ uint32_t g_Wbh[NCHK][16][128];
__device__ uint32_t g_Wbl[NCHK][16][128];

// ---------------------------------------------------------------------------
// mma.sync wrapper (baseline PTX, works on compute_103)
// ---------------------------------------------------------------------------
__device__ __forceinline__ void mma16816(float* c, uint32_t a0, uint32_t a1,
                                         uint32_t a2, uint32_t a3,
                                         uint32_t b0, uint32_t b1) {
    asm volatile(
        "mma.sync.aligned.m16n8k16.row.col.f32.bf16.bf16.f32 "
        "{%0,%1,%2,%3}, {%4,%5,%6,%7}, {%8,%9}, {%0,%1,%2,%3};"
        : "+f"(c[0]), "+f"(c[1]), "+f"(c[2]), "+f"(c[3])
        : "r"(a0), "r"(a1), "r"(a2), "r"(a3), "r"(b0), "r"(b1));
}

// ---------------------------------------------------------------------------
// k_packW: split W_e to bf16 hi/lo, k-paired layout (runs every launch)
// ---------------------------------------------------------------------------
__global__ void k_packW(const float* __restrict__ We) {
    int t = blockIdx.x * 256 + threadIdx.x;
    if (t >= NCHK * 16 * 128) return;
    int c  = t >> 11;
    int kp = (t >> 7) & 15;
    int n  = t & 127;
    int k0 = c * 32 + 2 * kp;
    float w0 = We[(size_t)k0 * CDIM + n];
    float w1 = We[(size_t)(k0 + 1) * CDIM + n];
    __nv_bfloat16 h0 = __float2bfloat16(w0);
    __nv_bfloat16 h1 = __float2bfloat16(w1);
    __nv_bfloat16 l0 = __float2bfloat16(w0 - __bfloat162float(h0));
    __nv_bfloat16 l1 = __float2bfloat16(w1 - __bfloat162float(h1));
    g_Wbh[c][kp][n] = (uint32_t)__bfloat16_as_ushort(h0) |
                      ((uint32_t)__bfloat16_as_ushort(h1) << 16);
    g_Wbl[c][kp][n] = (uint32_t)__bfloat16_as_ushort(l0) |
                      ((uint32_t)__bfloat16_as_ushort(l1) << 16);
}

// ---------------------------------------------------------------------------
// k_cb: virtual Cb + atom packing
// ---------------------------------------------------------------------------
__global__ void k_cb(const float* __restrict__ X) {
    int t = blockIdx.x * blockDim.x + threadIdx.x;
    if (t >= BB * LL) return;
    const float* x = X + (size_t)t * 12;
    float Nx = x[0],  Ny = x[1],  Nz = x[2];
    float Ax = x[3],  Ay = x[4],  Az = x[5];
    float Cx = x[6],  Cy = x[7],  Cz = x[8];
    float Ox = x[9],  Oy = x[10], Oz = x[11];
    float bx = Ax - Nx, by = Ay - Ny, bz = Az - Nz;
    float cx = Cx - Ax, cy = Cy - Ay, cz = Cz - Az;
    float ax = by * cz - bz * cy;
    float ay = bz * cx - bx * cz;
    float az = bx * cy - by * cx;
    const float wa = -0.58273431f, wb = 0.56802827f, wc = -0.54067466f;
    float Bx = wa * ax + wb * bx + wc * cx + Ax;
    float By = wa * ay + wb * by + wc * cy + Ay;
    float Bz = wa * az + wb * bz + wc * cz + Az;
    float* a = g_atoms + (size_t)t * 15;
    a[0]  = Ax; a[1]  = Ay; a[2]  = Az;
    a[3]  = Nx; a[4]  = Ny; a[5]  = Nz;
    a[6]  = Cx; a[7]  = Cy; a[8]  = Cz;
    a[9]  = Ox; a[10] = Oy; a[11] = Oz;
    a[12] = Bx; a[13] = By; a[14] = Bz;
    int bidx = t / LL, i = t - bidx * LL;
    g_ca[((size_t)bidx * 3 + 0) * LL + i] = Ax;
    g_ca[((size_t)bidx * 3 + 1) * LL + i] = Ay;
    g_ca[((size_t)bidx * 3 + 2) * LL + i] = Az;
}

// ---------------------------------------------------------------------------
// k_topk v2: per-warp local top-30 (no block syncs in extraction), then a
// single-warp 8-way merge. Exact: u64 keys (dist_bits<<32 | j) are unique,
// ascending extraction == jax.lax.top_k(-D) with lower-index tie-break.
// ---------------------------------------------------------------------------
__global__ void __launch_bounds__(256) k_topk(const float* __restrict__ mask,
                                              float* __restrict__ outI) {
    __shared__ float sx[LL], sy[LL], sz[LL], smk[LL];
    __shared__ float wred[8], sDmax;
    __shared__ unsigned long long lists[8][32];

    int row = blockIdx.x;
    int bb  = row >> 11;
    int i   = row & (LL - 1);
    int tid = threadIdx.x;
    int lane = tid & 31, warp = tid >> 5;

    const float* cax = g_ca + (size_t)bb * 3 * LL;
    for (int j = tid; j < LL; j += 256) {
        sx[j]  = cax[j];
        sy[j]  = cax[LL + j];
        sz[j]  = cax[2 * LL + j];
        smk[j] = mask[(size_t)bb * LL + j];
    }
    __syncthreads();

    float cx = sx[i], cy = sy[i], cz = sz[i], mi = smk[i];

    // warp w owns j in [w*256, w*256+256); lane stride 32
    float d[8], mk[8];
    float lmax = 0.f;
#pragma unroll
    for (int q = 0; q < 8; ++q) {
        int j = warp * 256 + q * 32 + lane;
        float dx = cx - sx[j], dy = cy - sy[j], dz = cz - sz[j];
        mk[q] = mi * smk[j];
        d[q] = mk[q] * sqrtf(dx * dx + dy * dy + dz * dz + 1e-6f);
        lmax = fmaxf(lmax, d[q]);
    }
#pragma unroll
    for (int off = 16; off; off >>= 1)
        lmax = fmaxf(lmax, __shfl_xor_sync(0xffffffffu, lmax, off));
    if (lane == 0) wred[warp] = lmax;
    __syncthreads();
    if (tid == 0) {
        float m = wred[0];
#pragma unroll
        for (int w = 1; w < 8; ++w) m = fmaxf(m, wred[w]);
        sDmax = m;
    }
    __syncthreads();
    float Dmax = sDmax;

    unsigned long long key[8];
#pragma unroll
    for (int q = 0; q < 8; ++q) {
        int j = warp * 256 + q * 32 + lane;
        float da = d[q] + (1.f - mk[q]) * Dmax;
        key[q] = ((unsigned long long)__float_as_uint(da) << 32) | (unsigned)j;
    }

    // warp-local top-30 (no block syncs)
    for (int s = 0; s < KK; ++s) {
        unsigned long long best = key[0];
#pragma unroll
        for (int q = 1; q < 8; ++q) if (key[q] < best) best = key[q];
#pragma unroll
        for (int off = 16; off; off >>= 1) {
            unsigned long long o2 = __shfl_xor_sync(0xffffffffu, best, off);
            if (o2 < best) best = o2;
        }
        if (lane == 0) lists[warp][s] = best;
        if (((int)(best & 31u)) == lane) {       // owner lane invalidates
            int slot = (int)((best >> 5) & 7u);
#pragma unroll
            for (int q = 0; q < 8; ++q)
                if (q == slot) key[q] = ~0ull;
        }
    }
    __syncthreads();

    // warp 0 merges 8 sorted lists of 30
    if (warp == 0) {
        unsigned long long cur = ~0ull;
        int ptr = 0;
        if (lane < 8) cur = lists[lane][0];
        for (int s = 0; s < KK; ++s) {
            unsigned long long m = cur;
#pragma unroll
            for (int off = 16; off; off >>= 1) {
                unsigned long long o2 = __shfl_xor_sync(0xffffffffu, m, off);
                if (o2 < m) m = o2;
            }
            if (lane == 0) {
                int jsel = (int)(m & 0xffffffffu);
                g_eidx[(size_t)row * KK + s] = jsel;
                if (outI) outI[(size_t)row * KK + s] = (float)jsel;
            }
            if (cur == m) {                      // unique winner (keys distinct)
                ++ptr;
                cur = (ptr < KK) ? lists[lane][ptr] : ~0ull;
            }
        }
    }
}

// ---------------------------------------------------------------------------
// k_edge3: bf16-split mma.sync edge GEMM, conflict-free smem strides.
// CTA = 2 rows -> M=64 edge slots, N=128, K=416 (13 chunks of 32).
// ---------------------------------------------------------------------------
__global__ void __launch_bounds__(128)
k_edge3(const int*   __restrict__ ridx,
        const int*   __restrict__ chains,
        const float* __restrict__ be,
        const float* __restrict__ ge,
        const float* __restrict__ bln,
        const float* __restrict__ Wpe,
        const float* __restrict__ bpe,
        float* __restrict__ outE)
{
    __shared__ float    s_ds[25 * 64];      // pair distances [pr][m]
    __shared__ float    s_pe[64 * 16];      // pos-emb [m][p]
    __shared__ float    s_ajs[60 * 16];     // neighbor atoms
    __shared__ float    s_ais[2 * 16];
    __shared__ int      s_idx[64];
    __shared__ int      s_dpe[64];
    __shared__ float    s_be[128], s_ge[128], s_bln[128];
    __shared__ uint32_t s_ah[16 * AS];      // A hi: [kp][m], stride 72
    __shared__ uint32_t s_al[16 * AS];
    __shared__ uint32_t s_bh[16 * BS];      // B hi: [kp][n], stride 136
    __shared__ uint32_t s_bl[16 * BS];
    __shared__ float    s_rsum[64 * 4], s_rsq[64 * 4];
    __shared__ float    s_mu[64], s_rs[64];

    int tid  = threadIdx.x;
    int lane = tid & 31, w = tid >> 5;
    int g    = lane >> 2, tig = lane & 3;
    int row0 = blockIdx.x * RPB;
    int bb   = row0 >> 11;

    // ---- prologue ----
    s_be[tid]  = be[tid];
    s_ge[tid]  = ge[tid];
    s_bln[tid] = bln[tid];
    if (tid < 64) {
        int r = tid >> 5, k = tid & 31;
        int grow = row0 + r;
        int li = grow & (LL - 1);
        int j = (k < KK) ? g_eidx[(size_t)grow * KK + k] : 0;
        s_idx[tid] = j;
        int ri = ridx[(size_t)bb * LL + li];
        int rj = ridx[(size_t)bb * LL + j];
        int ec = (chains[(size_t)bb * LL + li] == chains[(size_t)bb * LL + j]);
        int off = ri - rj + 32;
        off = off < 0 ? 0 : (off > 64 ? 64 : off);
        s_dpe[tid] = ec ? off : 65;
    }
    if (tid < 30) {
        int r = tid / 15, c = tid - r * 15;
        s_ais[r * 16 + c] = g_atoms[(size_t)(row0 + r) * 15 + c];
    }
    __syncthreads();

    for (int t = tid; t < 2 * KK * 15; t += 128) {
        int k2 = t / 15, c = t - k2 * 15;
        int r = k2 / KK, kk = k2 - r * KK;
        s_ajs[(r * KK + kk) * 16 + c] =
            g_atoms[((size_t)bb * LL + s_idx[r * 32 + kk]) * 15 + c];
    }
    __syncthreads();

    for (int t = tid; t < 25 * 64; t += 128) {       // pair distances
        int m = t & 63, pr = t >> 6;
        int r = m >> 5, k = m & 31;
        float dv = 0.f;
        if (k < KK) {
            int ai = pr / 5, aj = pr - (pr / 5) * 5;
            const float* A = s_ais + r * 16 + ai * 3;
            const float* J = s_ajs + (r * KK + k) * 16 + aj * 3;
            float dx = A[0] - J[0], dy = A[1] - J[1], dz = A[2] - J[2];
            dv = sqrtf(dx * dx + dy * dy + dz * dz + 1e-6f);
        }
        s_ds[pr * 64 + m] = dv;
    }
    for (int t = tid; t < 64 * 16; t += 128) {       // pos-emb
        int m = t & 63, p = t >> 6;
        int k = m & 31;
        float v = 0.f;
        if (k < KK) v = Wpe[s_dpe[m] * 16 + p] + bpe[p];
        s_pe[m * 16 + p] = v;
    }
    __syncthreads();

    // ---- accumulators ----
    float acc[4][4][4];
#pragma unroll
    for (int mt = 0; mt < 4; ++mt)
#pragma unroll
        for (int nt = 0; nt < 4; ++nt)
#pragma unroll
            for (int q = 0; q < 4; ++q) acc[mt][nt][q] = 0.f;

    const int am    = tid & 63;
    const int ahalf = tid >> 6;
    const int apad  = ((am & 31) >= KK);

    for (int c = 0; c < NCHK; ++c) {
        // B chunk copy (pre-split, pre-paired)
        {
            const uint32_t* gh = &g_Wbh[c][0][0];
            const uint32_t* gl = &g_Wbl[c][0][0];
#pragma unroll
            for (int q = 0; q < 16; ++q) {
                int e = tid + 128 * q;
                int kp = e >> 7, n = e & 127;
                s_bh[kp * BS + n] = gh[e];
                s_bl[kp * BS + n] = gl[e];
            }
        }
        // A chunk build: 8 kp x 2 features per thread
#pragma unroll
        for (int kp8 = 0; kp8 < 8; ++kp8) {
            int kp = ahalf * 8 + kp8;
            uint32_t hp = 0, lp = 0;
#pragma unroll
            for (int e = 0; e < 2; ++e) {
                int gf = c * 32 + 2 * kp + e;
                float v;
                if (gf < 16) {
                    v = s_pe[am * 16 + gf];
                } else {
                    int t2 = gf - 16;
                    int pr = t2 >> 4, mm = t2 & 15;
                    float dd = s_ds[pr * 64 + am];
                    float u = (dd - (2.0f + 1.33333333f * (float)mm)) * 0.8f;
                    v = __expf(-u * u);
                }
                if (apad) v = 0.f;
                __nv_bfloat16 h = __float2bfloat16(v);
                __nv_bfloat16 l = __float2bfloat16(v - __bfloat162float(h));
                hp |= (uint32_t)__bfloat16_as_ushort(h) << (16 * e);
                lp |= (uint32_t)__bfloat16_as_ushort(l) << (16 * e);
            }
            s_ah[kp * AS + am] = hp;
            s_al[kp * AS + am] = lp;
        }
        __syncthreads();

        // 2 k16 steps per chunk
#pragma unroll
        for (int s = 0; s < 2; ++s) {
            int kpa = s * 8 + tig;
            uint32_t ah[4][4], al[4][4];
#pragma unroll
            for (int mt = 0; mt < 4; ++mt) {
                int mb = mt * 16 + g;
                ah[mt][0] = s_ah[kpa * AS + mb];
                ah[mt][1] = s_ah[kpa * AS + mb + 8];
                ah[mt][2] = s_ah[(kpa + 4) * AS + mb];
                ah[mt][3] = s_ah[(kpa + 4) * AS + mb + 8];
                al[mt][0] = s_al[kpa * AS + mb];
                al[mt][1] = s_al[kpa * AS + mb + 8];
                al[mt][2] = s_al[(kpa + 4) * AS + mb];
                al[mt][3] = s_al[(kpa + 4) * AS + mb + 8];
            }
#pragma unroll
            for (int nt = 0; nt < 4; ++nt) {
                int nb = w * 32 + nt * 8 + g;
                uint32_t bh0 = s_bh[kpa * BS + nb];
                uint32_t bh1 = s_bh[(kpa + 4) * BS + nb];
                uint32_t bl0 = s_bl[kpa * BS + nb];
                uint32_t bl1 = s_bl[(kpa + 4) * BS + nb];
#pragma unroll
                for (int mt = 0; mt < 4; ++mt) {
                    mma16816(acc[mt][nt], ah[mt][0], ah[mt][1], ah[mt][2], ah[mt][3], bh0, bh1);
                    mma16816(acc[mt][nt], ah[mt][0], ah[mt][1], ah[mt][2], ah[mt][3], bl0, bl1);
                    mma16816(acc[mt][nt], al[mt][0], al[mt][1], al[mt][2], al[mt][3], bh0, bh1);
                }
            }
        }
        __syncthreads();
    }

    // ---- epilogue: + bias, LayerNorm over 128 channels per edge ----
#pragma unroll
    for (int mt = 0; mt < 4; ++mt)
#pragma unroll
        for (int nt = 0; nt < 4; ++nt) {
            int n0 = w * 32 + nt * 8 + tig * 2;
            acc[mt][nt][0] += s_be[n0];
            acc[mt][nt][1] += s_be[n0 + 1];
            acc[mt][nt][2] += s_be[n0];
            acc[mt][nt][3] += s_be[n0 + 1];
        }

#pragma unroll
    for (int mt = 0; mt < 4; ++mt) {
        float s0 = 0.f, q0 = 0.f, s1 = 0.f, q1 = 0.f;
#pragma unroll
        for (int nt = 0; nt < 4; ++nt) {
            float a0 = acc[mt][nt][0], a1 = acc[mt][nt][1];
            float a2 = acc[mt][nt][2], a3 = acc[mt][nt][3];
            s0 += a0 + a1;  q0 += a0 * a0 + a1 * a1;
            s1 += a2 + a3;  q1 += a2 * a2 + a3 * a3;
        }
#pragma unroll
        for (int off = 1; off < 4; off <<= 1) {
            s0 += __shfl_xor_sync(0xffffffffu, s0, off);
            q0 += __shfl_xor_sync(0xffffffffu, q0, off);
            s1 += __shfl_xor_sync(0xffffffffu, s1, off);
            q1 += __shfl_xor_sync(0xffffffffu, q1, off);
        }
        if (tig == 0) {
            int m0 = mt * 16 + g;
            s_rsum[m0 * 4 + w] = s0;  s_rsq[m0 * 4 + w] = q0;
            s_rsum[(m0 + 8) * 4 + w] = s1;  s_rsq[(m0 + 8) * 4 + w] = q1;
        }
    }
    __syncthreads();
    if (tid < 64) {
        float s1 = s_rsum[tid * 4] + s_rsum[tid * 4 + 1] +
                   s_rsum[tid * 4 + 2] + s_rsum[tid * 4 + 3];
        float q1 = s_rsq[tid * 4] + s_rsq[tid * 4 + 1] +
                   s_rsq[tid * 4 + 2] + s_rsq[tid * 4 + 3];
        float mu = s1 * (1.f / 128.f);
        float var = q1 * (1.f / 128.f) - mu * mu;
        s_mu[tid] = mu;
        s_rs[tid] = rsqrtf(var + 1e-5f);
    }
    __syncthreads();

#pragma unroll
    for (int mt = 0; mt < 4; ++mt) {
#pragma unroll
        for (int half = 0; half < 2; ++half) {
            int m = mt * 16 + g + 8 * half;
            int k = m & 31;
            if (k >= KK) continue;
            int r = m >> 5;
            float mu = s_mu[m], rs = s_rs[m];
            size_t ebase = (((size_t)(row0 + r)) * KK + k) * CDIM;
#pragma unroll
            for (int nt = 0; nt < 4; ++nt) {
                int n0 = w * 32 + nt * 8 + tig * 2;
                float v0 = acc[mt][nt][2 * half];
                float v1 = acc[mt][nt][2 * half + 1];
                float2 o;
                o.x = (v0 - mu) * rs * s_ge[n0]     + s_bln[n0];
                o.y = (v1 - mu) * rs * s_ge[n0 + 1] + s_bln[n0 + 1];
                *(float2*)(outE + ebase + n0) = o;
            }
        }
    }
}

// ---------------------------------------------------------------------------
// Launch
// ---------------------------------------------------------------------------
extern "C" void kernel_launch(void* const* d_in, const int* in_sizes, int n_in,
                              void* d_out, int out_size) {
    const float* X      = (const float*)d_in[0];
    const float* mask   = (const float*)d_in[1];
    const int*   ridx   = (const int*)  d_in[2];
    const int*   chains = (const int*)  d_in[3];
    const float* We     = (const float*)d_in[4];
    const float* be     = (const float*)d_in[5];
    const float* ge     = (const float*)d_in[6];
    const float* beln   = (const float*)d_in[7];
    const float* Wpe    = (const float*)d_in[8];
    const float* bpe    = (const float*)d_in[9];
    float* out = (float*)d_out;

    const size_t E_ELEMS = (size_t)BB * LL * KK * CDIM;
    const size_t I_ELEMS = (size_t)BB * LL * KK;
    float* outI = ((size_t)out_size >= E_ELEMS + I_ELEMS) ? (out + E_ELEMS)
                                                          : nullptr;

    k_packW<<<(NCHK * 16 * 128 + 255) / 256, 256>>>(We);
    k_cb<<<(BB * LL + 255) / 256, 256>>>(X);
    k_topk<<<BB * LL, 256>>>(mask, outI);
    k_edge3<<<BB * LL / RPB, 128>>>(ridx, chains, be, ge, beln, Wpe, bpe, out);
}

// round 16
// speedup vs baseline: 1.8624x; 1.0655x over previous
#include <cuda_runtime.h>
#include <cuda_bf16.h>
#include <cstdint>
#include <cstddef>

#define BB   8
#define LL   2048
#define KK   30
#define FDIM 416
#define CDIM 128
#define RPB  2            // residue rows per CTA in k_edge3 (M = 64)
#define NCHK 13           // K chunks of 32 features (13*32 = 416)
#define AS   72           // A smem stride (u32): 72 mod 32 = 8 -> conflict-free

// ---------------------------------------------------------------------------
// Device scratch
// ---------------------------------------------------------------------------
__device__ float g_atoms[(size_t)BB * LL * 15];
__device__ float g_ca[(size_t)BB * 3 * LL];
__device__ int   g_eidx[(size_t)BB * LL * KK];
// Fragment-order W_e: g_Wf[c][s][w][lane][nt] = {bh(kpa), bh(kpa+4), bl(kpa), bl(kpa+4)}
// with kpa = 8s + (lane&3), n = 32w + 8nt + (lane>>2); k-pair {2kp, 2kp+1} of chunk c.
__device__ uint4 g_Wf[NCHK][2][4][32][4];

// ---------------------------------------------------------------------------
// mma.sync wrapper (baseline PTX, works on compute_103)
// ---------------------------------------------------------------------------
__device__ __forceinline__ void mma16816(float* c, uint32_t a0, uint32_t a1,
                                         uint32_t a2, uint32_t a3,
                                         uint32_t b0, uint32_t b1) {
    asm volatile(
        "mma.sync.aligned.m16n8k16.row.col.f32.bf16.bf16.f32 "
        "{%0,%1,%2,%3}, {%4,%5,%6,%7}, {%8,%9}, {%0,%1,%2,%3};"
        : "+f"(c[0]), "+f"(c[1]), "+f"(c[2]), "+f"(c[3])
        : "r"(a0), "r"(a1), "r"(a2), "r"(a3), "r"(b0), "r"(b1));
}

__device__ __forceinline__ uint32_t packpair_hi(float w0, float w1) {
    __nv_bfloat16 h0 = __float2bfloat16(w0);
    __nv_bfloat16 h1 = __float2bfloat16(w1);
    return (uint32_t)__bfloat16_as_ushort(h0) |
           ((uint32_t)__bfloat16_as_ushort(h1) << 16);
}
__device__ __forceinline__ uint32_t packpair_lo(float w0, float w1) {
    __nv_bfloat16 h0 = __float2bfloat16(w0);
    __nv_bfloat16 h1 = __float2bfloat16(w1);
    __nv_bfloat16 l0 = __float2bfloat16(w0 - __bfloat162float(h0));
    __nv_bfloat16 l1 = __float2bfloat16(w1 - __bfloat162float(h1));
    return (uint32_t)__bfloat16_as_ushort(l0) |
           ((uint32_t)__bfloat16_as_ushort(l1) << 16);
}

// ---------------------------------------------------------------------------
// k_packW: fragment-order bf16 hi/lo split of W_e (runs every launch)
// ---------------------------------------------------------------------------
__global__ void k_packW(const float* __restrict__ We) {
    int t = blockIdx.x * 256 + threadIdx.x;
    if (t >= NCHK * 2 * 4 * 32 * 4) return;     // 13312
    int nt   = t & 3;
    int lane = (t >> 2) & 31;
    int w    = (t >> 7) & 3;
    int s    = (t >> 9) & 1;
    int c    = t >> 10;
    int g = lane >> 2, tig = lane & 3;
    int kpa = 8 * s + tig;
    int n   = 32 * w + 8 * nt + g;
    int ka = c * 32 + 2 * kpa;          // k-pair for bh0/bl0
    int kb = ka + 8;                    // k-pair for bh1/bl1 (kpa+4)
    float a0 = We[(size_t)ka * CDIM + n];
    float a1 = We[(size_t)(ka + 1) * CDIM + n];
    float b0 = We[(size_t)kb * CDIM + n];
    float b1 = We[(size_t)(kb + 1) * CDIM + n];
    uint4 o;
    o.x = packpair_hi(a0, a1);
    o.y = packpair_hi(b0, b1);
    o.z = packpair_lo(a0, a1);
    o.w = packpair_lo(b0, b1);
    g_Wf[c][s][w][lane][nt] = o;
}

// ---------------------------------------------------------------------------
// k_cb: virtual Cb + atom packing (R9-verified)
// ---------------------------------------------------------------------------
__global__ void k_cb(const float* __restrict__ X) {
    int t = blockIdx.x * blockDim.x + threadIdx.x;
    if (t >= BB * LL) return;
    const float* x = X + (size_t)t * 12;
    float Nx = x[0],  Ny = x[1],  Nz = x[2];
    float Ax = x[3],  Ay = x[4],  Az = x[5];
    float Cx = x[6],  Cy = x[7],  Cz = x[8];
    float Ox = x[9],  Oy = x[10], Oz = x[11];
    float bx = Ax - Nx, by = Ay - Ny, bz = Az - Nz;
    float cx = Cx - Ax, cy = Cy - Ay, cz = Cz - Az;
    float ax = by * cz - bz * cy;
    float ay = bz * cx - bx * cz;
    float az = bx * cy - by * cx;
    const float wa = -0.58273431f, wb = 0.56802827f, wc = -0.54067466f;
    float Bx = wa * ax + wb * bx + wc * cx + Ax;
    float By = wa * ay + wb * by + wc * cy + Ay;
    float Bz = wa * az + wb * bz + wc * cz + Az;
    float* a = g_atoms + (size_t)t * 15;
    a[0]  = Ax; a[1]  = Ay; a[2]  = Az;
    a[3]  = Nx; a[4]  = Ny; a[5]  = Nz;
    a[6]  = Cx; a[7]  = Cy; a[8]  = Cz;
    a[9]  = Ox; a[10] = Oy; a[11] = Oz;
    a[12] = Bx; a[13] = By; a[14] = Bz;
    int bidx = t / LL, i = t - bidx * LL;
    g_ca[((size_t)bidx * 3 + 0) * LL + i] = Ax;
    g_ca[((size_t)bidx * 3 + 1) * LL + i] = Ay;
    g_ca[((size_t)bidx * 3 + 2) * LL + i] = Az;
}

// ---------------------------------------------------------------------------
// k_topk v2 (R9-verified): per-warp local top-30, then single-warp 8-way merge
// ---------------------------------------------------------------------------
__global__ void __launch_bounds__(256) k_topk(const float* __restrict__ mask,
                                              float* __restrict__ outI) {
    __shared__ float sx[LL], sy[LL], sz[LL], smk[LL];
    __shared__ float wred[8], sDmax;
    __shared__ unsigned long long lists[8][32];

    int row = blockIdx.x;
    int bb  = row >> 11;
    int i   = row & (LL - 1);
    int tid = threadIdx.x;
    int lane = tid & 31, warp = tid >> 5;

    const float* cax = g_ca + (size_t)bb * 3 * LL;
    for (int j = tid; j < LL; j += 256) {
        sx[j]  = cax[j];
        sy[j]  = cax[LL + j];
        sz[j]  = cax[2 * LL + j];
        smk[j] = mask[(size_t)bb * LL + j];
    }
    __syncthreads();

    float cx = sx[i], cy = sy[i], cz = sz[i], mi = smk[i];

    float d[8], mk[8];
    float lmax = 0.f;
#pragma unroll
    for (int q = 0; q < 8; ++q) {
        int j = warp * 256 + q * 32 + lane;
        float dx = cx - sx[j], dy = cy - sy[j], dz = cz - sz[j];
        mk[q] = mi * smk[j];
        d[q] = mk[q] * sqrtf(dx * dx + dy * dy + dz * dz + 1e-6f);
        lmax = fmaxf(lmax, d[q]);
    }
#pragma unroll
    for (int off = 16; off; off >>= 1)
        lmax = fmaxf(lmax, __shfl_xor_sync(0xffffffffu, lmax, off));
    if (lane == 0) wred[warp] = lmax;
    __syncthreads();
    if (tid == 0) {
        float m = wred[0];
#pragma unroll
        for (int w = 1; w < 8; ++w) m = fmaxf(m, wred[w]);
        sDmax = m;
    }
    __syncthreads();
    float Dmax = sDmax;

    unsigned long long key[8];
#pragma unroll
    for (int q = 0; q < 8; ++q) {
        int j = warp * 256 + q * 32 + lane;
        float da = d[q] + (1.f - mk[q]) * Dmax;
        key[q] = ((unsigned long long)__float_as_uint(da) << 32) | (unsigned)j;
    }

    // warp-local top-30 (no block syncs)
    for (int s = 0; s < KK; ++s) {
        unsigned long long best = key[0];
#pragma unroll
        for (int q = 1; q < 8; ++q) if (key[q] < best) best = key[q];
#pragma unroll
        for (int off = 16; off; off >>= 1) {
            unsigned long long o2 = __shfl_xor_sync(0xffffffffu, best, off);
            if (o2 < best) best = o2;
        }
        if (lane == 0) lists[warp][s] = best;
        if (((int)(best & 31u)) == lane) {       // owner lane invalidates
            int slot = (int)((best >> 5) & 7u);
#pragma unroll
            for (int q = 0; q < 8; ++q)
                if (q == slot) key[q] = ~0ull;
        }
    }
    __syncthreads();

    // warp 0 merges 8 sorted lists of 30
    if (warp == 0) {
        unsigned long long cur = ~0ull;
        int ptr = 0;
        if (lane < 8) cur = lists[lane][0];
        for (int s = 0; s < KK; ++s) {
            unsigned long long m = cur;
#pragma unroll
            for (int off = 16; off; off >>= 1) {
                unsigned long long o2 = __shfl_xor_sync(0xffffffffu, m, off);
                if (o2 < m) m = o2;
            }
            if (lane == 0) {
                int jsel = (int)(m & 0xffffffffu);
                g_eidx[(size_t)row * KK + s] = jsel;
                if (outI) outI[(size_t)row * KK + s] = (float)jsel;
            }
            if (cur == m) {                      // unique winner
                ++ptr;
                cur = (ptr < KK) ? lists[lane][ptr] : ~0ull;
            }
        }
    }
}

// ---------------------------------------------------------------------------
// k_edge3 v2.1: R9's passing GEMM with B moved from smem to L2-resident
// fragment-order global loads. A path (stride-72 smem + LDS.32) unchanged.
// CTA = 2 rows -> M=64 edge slots, N=128, K=416 (13 chunks of 32).
// ---------------------------------------------------------------------------
__global__ void __launch_bounds__(128)
k_edge3(const int*   __restrict__ ridx,
        const int*   __restrict__ chains,
        const float* __restrict__ be,
        const float* __restrict__ ge,
        const float* __restrict__ bln,
        const float* __restrict__ Wpe,
        const float* __restrict__ bpe,
        float* __restrict__ outE)
{
    __shared__ float    s_ds[25 * 64];      // pair distances [pr][m]
    __shared__ float    s_pe[64 * 16];      // pos-emb [m][p]
    __shared__ float    s_ajs[60 * 16];     // neighbor atoms
    __shared__ float    s_ais[2 * 16];
    __shared__ int      s_idx[64];
    __shared__ int      s_dpe[64];
    __shared__ float    s_be[128], s_ge[128], s_bln[128];
    __shared__ uint32_t s_ah[16 * AS];      // A hi: [kp][m], stride 72
    __shared__ uint32_t s_al[16 * AS];
    __shared__ float    s_rsum[64 * 4], s_rsq[64 * 4];
    __shared__ float    s_mu[64], s_rs[64];

    int tid  = threadIdx.x;
    int lane = tid & 31, w = tid >> 5;
    int g    = lane >> 2, tig = lane & 3;
    int row0 = blockIdx.x * RPB;
    int bb   = row0 >> 11;

    // ---- prologue (R9-verified) ----
    s_be[tid]  = be[tid];
    s_ge[tid]  = ge[tid];
    s_bln[tid] = bln[tid];
    if (tid < 64) {
        int r = tid >> 5, k = tid & 31;
        int grow = row0 + r;
        int li = grow & (LL - 1);
        int j = (k < KK) ? g_eidx[(size_t)grow * KK + k] : 0;
        s_idx[tid] = j;
        int ri = ridx[(size_t)bb * LL + li];
        int rj = ridx[(size_t)bb * LL + j];
        int ec = (chains[(size_t)bb * LL + li] == chains[(size_t)bb * LL + j]);
        int off = ri - rj + 32;
        off = off < 0 ? 0 : (off > 64 ? 64 : off);
        s_dpe[tid] = ec ? off : 65;
    }
    if (tid < 30) {
        int r = tid / 15, c = tid - r * 15;
        s_ais[r * 16 + c] = g_atoms[(size_t)(row0 + r) * 15 + c];
    }
    __syncthreads();

    for (int t = tid; t < 2 * KK * 15; t += 128) {
        int k2 = t / 15, c = t - k2 * 15;
        int r = k2 / KK, kk = k2 - r * KK;
        s_ajs[(r * KK + kk) * 16 + c] =
            g_atoms[((size_t)bb * LL + s_idx[r * 32 + kk]) * 15 + c];
    }
    __syncthreads();

    for (int t = tid; t < 25 * 64; t += 128) {       // pair distances
        int m = t & 63, pr = t >> 6;
        int r = m >> 5, k = m & 31;
        float dv = 0.f;
        if (k < KK) {
            int ai = pr / 5, aj = pr - (pr / 5) * 5;
            const float* A = s_ais + r * 16 + ai * 3;
            const float* J = s_ajs + (r * KK + k) * 16 + aj * 3;
            float dx = A[0] - J[0], dy = A[1] - J[1], dz = A[2] - J[2];
            dv = sqrtf(dx * dx + dy * dy + dz * dz + 1e-6f);
        }
        s_ds[pr * 64 + m] = dv;
    }
    for (int t = tid; t < 64 * 16; t += 128) {       // pos-emb
        int m = t & 63, p = t >> 6;
        int k = m & 31;
        float v = 0.f;
        if (k < KK) v = Wpe[s_dpe[m] * 16 + p] + bpe[p];
        s_pe[m * 16 + p] = v;
    }
    __syncthreads();

    // ---- accumulators ----
    float acc[4][4][4];
#pragma unroll
    for (int mt = 0; mt < 4; ++mt)
#pragma unroll
        for (int nt = 0; nt < 4; ++nt)
#pragma unroll
            for (int q = 0; q < 4; ++q) acc[mt][nt][q] = 0.f;

    const int am    = tid & 63;
    const int ahalf = tid >> 6;
    const int apad  = ((am & 31) >= KK);

    for (int c = 0; c < NCHK; ++c) {
        // B fragments straight from global (L2-resident, fragment-ordered).
        // Issued before the A build so the LDGs overlap with MUFU/FMA work.
        uint4 bfr[8];
#pragma unroll
        for (int s = 0; s < 2; ++s)
#pragma unroll
            for (int nt = 0; nt < 4; ++nt)
                bfr[s * 4 + nt] = g_Wf[c][s][w][lane][nt];

        // A chunk build: 8 kp x 2 features per thread (R9-verified path)
#pragma unroll
        for (int kp8 = 0; kp8 < 8; ++kp8) {
            int kp = ahalf * 8 + kp8;
            uint32_t hp = 0, lp = 0;
            float v2[2];
#pragma unroll
            for (int e = 0; e < 2; ++e) {
                int gf = c * 32 + 2 * kp + e;
                float v;
                if (gf < 16) {
                    v = s_pe[am * 16 + gf];
                } else {
                    int t2 = gf - 16;
                    int pr = t2 >> 4, mm = t2 & 15;
                    float dd = s_ds[pr * 64 + am];
                    float u = (dd - (2.0f + 1.33333333f * (float)mm)) * 0.8f;
                    v = __expf(-u * u);
                }
                if (apad) v = 0.f;
                v2[e] = v;
            }
            hp = packpair_hi(v2[0], v2[1]);
            lp = packpair_lo(v2[0], v2[1]);
            s_ah[kp * AS + am] = hp;
            s_al[kp * AS + am] = lp;
        }
        __syncthreads();

        // 2 k16 steps per chunk
#pragma unroll
        for (int s = 0; s < 2; ++s) {
            int kpa = s * 8 + tig;
            uint32_t ah[4][4], al[4][4];
#pragma unroll
            for (int mt = 0; mt < 4; ++mt) {
                int mb = mt * 16 + g;
                ah[mt][0] = s_ah[kpa * AS + mb];
                ah[mt][1] = s_ah[kpa * AS + mb + 8];
                ah[mt][2] = s_ah[(kpa + 4) * AS + mb];
                ah[mt][3] = s_ah[(kpa + 4) * AS + mb + 8];
                al[mt][0] = s_al[kpa * AS + mb];
                al[mt][1] = s_al[kpa * AS + mb + 8];
                al[mt][2] = s_al[(kpa + 4) * AS + mb];
                al[mt][3] = s_al[(kpa + 4) * AS + mb + 8];
            }
#pragma unroll
            for (int nt = 0; nt < 4; ++nt) {
                uint4 b = bfr[s * 4 + nt];
#pragma unroll
                for (int mt = 0; mt < 4; ++mt) {
                    mma16816(acc[mt][nt], ah[mt][0], ah[mt][1], ah[mt][2], ah[mt][3], b.x, b.y);
                    mma16816(acc[mt][nt], ah[mt][0], ah[mt][1], ah[mt][2], ah[mt][3], b.z, b.w);
                    mma16816(acc[mt][nt], al[mt][0], al[mt][1], al[mt][2], al[mt][3], b.x, b.y);
                }
            }
        }
        __syncthreads();
    }

    // ---- epilogue: + bias, LayerNorm over 128 channels per edge (R9) ----
#pragma unroll
    for (int mt = 0; mt < 4; ++mt)
#pragma unroll
        for (int nt = 0; nt < 4; ++nt) {
            int n0 = w * 32 + nt * 8 + tig * 2;
            acc[mt][nt][0] += s_be[n0];
            acc[mt][nt][1] += s_be[n0 + 1];
            acc[mt][nt][2] += s_be[n0];
            acc[mt][nt][3] += s_be[n0 + 1];
        }

#pragma unroll
    for (int mt = 0; mt < 4; ++mt) {
        float s0 = 0.f, q0 = 0.f, s1 = 0.f, q1 = 0.f;
#pragma unroll
        for (int nt = 0; nt < 4; ++nt) {
            float a0 = acc[mt][nt][0], a1 = acc[mt][nt][1];
            float a2 = acc[mt][nt][2], a3 = acc[mt][nt][3];
            s0 += a0 + a1;  q0 += a0 * a0 + a1 * a1;
            s1 += a2 + a3;  q1 += a2 * a2 + a3 * a3;
        }
#pragma unroll
        for (int off = 1; off < 4; off <<= 1) {
            s0 += __shfl_xor_sync(0xffffffffu, s0, off);
            q0 += __shfl_xor_sync(0xffffffffu, q0, off);
            s1 += __shfl_xor_sync(0xffffffffu, s1, off);
            q1 += __shfl_xor_sync(0xffffffffu, q1, off);
        }
        if (tig == 0) {
            int m0 = mt * 16 + g;
            s_rsum[m0 * 4 + w] = s0;  s_rsq[m0 * 4 + w] = q0;
            s_rsum[(m0 + 8) * 4 + w] = s1;  s_rsq[(m0 + 8) * 4 + w] = q1;
        }
    }
    __syncthreads();
    if (tid < 64) {
        float s1 = s_rsum[tid * 4] + s_rsum[tid * 4 + 1] +
                   s_rsum[tid * 4 + 2] + s_rsum[tid * 4 + 3];
        float q1 = s_rsq[tid * 4] + s_rsq[tid * 4 + 1] +
                   s_rsq[tid * 4 + 2] + s_rsq[tid * 4 + 3];
        float mu = s1 * (1.f / 128.f);
        float var = q1 * (1.f / 128.f) - mu * mu;
        s_mu[tid] = mu;
        s_rs[tid] = rsqrtf(var + 1e-5f);
    }
    __syncthreads();

#pragma unroll
    for (int mt = 0; mt < 4; ++mt) {
#pragma unroll
        for (int half = 0; half < 2; ++half) {
            int m = mt * 16 + g + 8 * half;
            int k = m & 31;
            if (k >= KK) continue;
            int r = m >> 5;
            float mu = s_mu[m], rs = s_rs[m];
            size_t ebase = (((size_t)(row0 + r)) * KK + k) * CDIM;
#pragma unroll
            for (int nt = 0; nt < 4; ++nt) {
                int n0 = w * 32 + nt * 8 + tig * 2;
                float v0 = acc[mt][nt][2 * half];
                float v1 = acc[mt][nt][2 * half + 1];
                float2 o;
                o.x = (v0 - mu) * rs * s_ge[n0]     + s_bln[n0];
                o.y = (v1 - mu) * rs * s_ge[n0 + 1] + s_bln[n0 + 1];
                *(float2*)(outE + ebase + n0) = o;
            }
        }
    }
}

// ---------------------------------------------------------------------------
// Launch
// ---------------------------------------------------------------------------
extern "C" void kernel_launch(void* const* d_in, const int* in_sizes, int n_in,
                              void* d_out, int out_size) {
    const float* X      = (const float*)d_in[0];
    const float* mask   = (const float*)d_in[1];
    const int*   ridx   = (const int*)  d_in[2];
    const int*   chains = (const int*)  d_in[3];
    const float* We     = (const float*)d_in[4];
    const float* be     = (const float*)d_in[5];
    const float* ge     = (const float*)d_in[6];
    const float* beln   = (const float*)d_in[7];
    const float* Wpe    = (const float*)d_in[8];
    const float* bpe    = (const float*)d_in[9];
    float* out = (float*)d_out;

    const size_t E_ELEMS = (size_t)BB * LL * KK * CDIM;
    const size_t I_ELEMS = (size_t)BB * LL * KK;
    float* outI = ((size_t)out_size >= E_ELEMS + I_ELEMS) ? (out + E_ELEMS)
                                                          : nullptr;

    k_packW<<<(NCHK * 2 * 4 * 32 * 4 + 255) / 256, 256>>>(We);
    k_cb<<<(BB * LL + 255) / 256, 256>>>(X);
    k_topk<<<BB * LL, 256>>>(mask, outI);
    k_edge3<<<BB * LL / RPB, 128>>>(ridx, chains, be, ge, beln, Wpe, bpe, out);
}